// round 8
// baseline (speedup 1.0000x reference)
#include <cuda_runtime.h>
#include <math.h>

#define NB   16
#define NT   1000
#define NF   512
#define NH   512
#define NSEQ 2000
#define MROWS (NB*NT)   /* 16000 */
#define DOUT  1024      /* 2H */

#define GBM 128
#define GBN 128
#define GBK 16

typedef unsigned long long ull;

// ---------------- f32x2 packed helpers (sm_100+) ----------------
__device__ __forceinline__ ull f2pk(float lo, float hi) {
    ull r; asm("mov.b64 %0, {%1, %2};" : "=l"(r) : "f"(lo), "f"(hi)); return r;
}
__device__ __forceinline__ float2 f2unpk(ull v) {
    float2 r; asm("mov.b64 {%0, %1}, %2;" : "=f"(r.x), "=f"(r.y) : "l"(v)); return r;
}
__device__ __forceinline__ void fma2(ull& d, ull a, ull b) {
    asm("fma.rn.f32x2 %0, %1, %2, %0;" : "+l"(d) : "l"(a), "l"(b));
}
__device__ __forceinline__ void st_relaxed_gpu(float* p, float v) {
    asm volatile("st.relaxed.gpu.global.f32 [%0], %1;" :: "l"(p), "f"(v) : "memory");
}

// ---------------- scratch (device globals; no runtime allocation) ----------------
__device__ float g_Wpre[MROWS*DOUT];        // [b][t][n]  BN(x@[Wz;Wh]^T+b)
__device__ float g_H[NSEQ*NB*NH];           // [s][b][j]  all hidden states
__device__ float g_ln[MROWS*DOUT];          // layernorm output
__device__ float g_hbuf[8][2][2*NH];        // [group][parity][b*512+j]
__device__ int   g_arrv[8];                 // per-group arrival counters
__device__ float g_scale[DOUT];             // folded BN scale
__device__ float g_shift[DOUT];             // folded BN shift (incl. gemm bias)

// ---------------- setup: fold BN + bias, reset barriers ----------------
__global__ void setup_kernel(const float* __restrict__ bz, const float* __restrict__ bh,
                             const float* __restrict__ zg, const float* __restrict__ zb,
                             const float* __restrict__ zm, const float* __restrict__ zv,
                             const float* __restrict__ hg, const float* __restrict__ hb,
                             const float* __restrict__ hm, const float* __restrict__ hv)
{
    int n = blockIdx.x * blockDim.x + threadIdx.x;
    if (n < 512) {
        float sc = zg[n] * rsqrtf(zv[n] + 1e-5f);
        g_scale[n] = sc;
        g_shift[n] = (bz[n] - zm[n]) * sc + zb[n];
    } else if (n < 1024) {
        int m = n - 512;
        float sc = hg[m] * rsqrtf(hv[m] + 1e-5f);
        g_scale[n] = sc;
        g_shift[n] = (bh[m] - hm[m]) * sc + hb[m];
    }
    if (blockIdx.x == 0 && threadIdx.x < 8) g_arrv[threadIdx.x] = 0;
}

__global__ void dummy_kernel() {}   // shifts the ncu capture slot onto ligru

// ---------------- 128x128x16 f32x2 GEMM: C[M,N] = A[M,K] * Brow[n][K] ----------------
template<int MODE>
__global__ __launch_bounds__(256, 2)
void gemm_nt2(const float* __restrict__ A,
              const float* __restrict__ B0, const float* __restrict__ B1, int nsplit,
              float* __restrict__ C, int M, int N, int K,
              const float* __restrict__ e0, const float* __restrict__ e1)
{
    __shared__ float As[2][GBK][GBM + 4];
    __shared__ float Bs[2][GBK][GBN + 4];

    const int m0 = blockIdx.x * GBM;
    const int n0 = blockIdx.y * GBN;
    const int tid = threadIdx.x;

    const int lr  = tid >> 1;          // 0..127
    const int lks = (tid & 1) * 8;     // 0 or 8

    const int tx = tid & 15;           // n
    const int ty = tid >> 4;           // m

    const int nrow = n0 + lr;
    const float* brow = (nrow < nsplit) ? (B0 + (size_t)nrow * K)
                                        : (B1 + (size_t)(nrow - nsplit) * K);
    const float* arow = A + (size_t)(m0 + lr) * K;

    ull acc[2][4][2][2];
#pragma unroll
    for (int a = 0; a < 2; a++)
#pragma unroll
        for (int i = 0; i < 4; i++)
#pragma unroll
            for (int b = 0; b < 2; b++) { acc[a][i][b][0] = 0ull; acc[a][i][b][1] = 0ull; }

    const int nt = K / GBK;
    float4 ga0, ga1, gb0, gb1;

    ga0 = *(const float4*)(arow + lks);     ga1 = *(const float4*)(arow + lks + 4);
    gb0 = *(const float4*)(brow + lks);     gb1 = *(const float4*)(brow + lks + 4);
#pragma unroll
    for (int i = 0; i < 4; i++) {
        As[0][lks + i][lr]     = ((const float*)&ga0)[i];
        As[0][lks + 4 + i][lr] = ((const float*)&ga1)[i];
        Bs[0][lks + i][lr]     = ((const float*)&gb0)[i];
        Bs[0][lks + 4 + i][lr] = ((const float*)&gb1)[i];
    }
    __syncthreads();

    for (int t = 0; t < nt; t++) {
        const int cur = t & 1;
        if (t + 1 < nt) {
            const int k0 = (t + 1) * GBK;
            ga0 = *(const float4*)(arow + k0 + lks); ga1 = *(const float4*)(arow + k0 + lks + 4);
            gb0 = *(const float4*)(brow + k0 + lks); gb1 = *(const float4*)(brow + k0 + lks + 4);
        }

#pragma unroll
        for (int k = 0; k < GBK; k++) {
            float4 a0 = *(const float4*)&As[cur][k][ty * 4];
            float4 a1 = *(const float4*)&As[cur][k][64 + ty * 4];
            float4 b0 = *(const float4*)&Bs[cur][k][tx * 4];
            float4 b1 = *(const float4*)&Bs[cur][k][64 + tx * 4];
            ull bp[2][2] = { { f2pk(b0.x, b0.y), f2pk(b0.z, b0.w) },
                             { f2pk(b1.x, b1.y), f2pk(b1.z, b1.w) } };
            float am[2][4] = { { a0.x, a0.y, a0.z, a0.w },
                               { a1.x, a1.y, a1.z, a1.w } };
#pragma unroll
            for (int mb = 0; mb < 2; mb++)
#pragma unroll
                for (int i = 0; i < 4; i++) {
                    ull ap = f2pk(am[mb][i], am[mb][i]);
#pragma unroll
                    for (int nb = 0; nb < 2; nb++) {
                        fma2(acc[mb][i][nb][0], ap, bp[nb][0]);
                        fma2(acc[mb][i][nb][1], ap, bp[nb][1]);
                    }
                }
        }

        if (t + 1 < nt) {
            const int nxt = (t + 1) & 1;
#pragma unroll
            for (int i = 0; i < 4; i++) {
                As[nxt][lks + i][lr]     = ((const float*)&ga0)[i];
                As[nxt][lks + 4 + i][lr] = ((const float*)&ga1)[i];
                Bs[nxt][lks + i][lr]     = ((const float*)&gb0)[i];
                Bs[nxt][lks + 4 + i][lr] = ((const float*)&gb1)[i];
            }
            __syncthreads();
        }
    }

#pragma unroll
    for (int mb = 0; mb < 2; mb++)
#pragma unroll
        for (int i = 0; i < 4; i++) {
            const int m = m0 + mb * 64 + ty * 4 + i;
#pragma unroll
            for (int nb = 0; nb < 2; nb++) {
                const int n = n0 + nb * 64 + tx * 4;
                float2 p0 = f2unpk(acc[mb][i][nb][0]);
                float2 p1 = f2unpk(acc[mb][i][nb][1]);
                float4 v = make_float4(p0.x, p0.y, p1.x, p1.y);
                if (MODE == 0) {
                    float4 s = *(const float4*)&e0[n];
                    float4 h = *(const float4*)&e1[n];
                    v.x = v.x * s.x + h.x; v.y = v.y * s.y + h.y;
                    v.z = v.z * s.z + h.z; v.w = v.w * s.w + h.w;
                } else {
                    float4 bb = *(const float4*)&e0[n];
                    v.x = tanhf(v.x + bb.x); v.y = tanhf(v.y + bb.y);
                    v.z = tanhf(v.z + bb.z); v.w = tanhf(v.w + bb.w);
                }
                *(float4*)&C[(size_t)m * N + n] = v;
            }
        }
}

// ---------------- persistent LiGRU recurrence, warp-local reduce + lean sync ----------------
// 128 CTAs: 8 groups x 16 CTAs. Group g owns GLOBAL batch rows {2g, 2g+1}.
// CTA c owns j in [32c, 32c+32).
// Thread (w=warp, l=lane): jl = w*4 + (l>>3), gate = (l>>2)&1, ks = l&3.
// Thread's k-set: interleaved 16B granules {4q+ks, q=0..31}  (conflict-free LDS)
__global__ __launch_bounds__(256, 1)
void ligru_kernel(const float* __restrict__ U)
{
    const int g   = blockIdx.x >> 4;
    const int c   = blockIdx.x & 15;
    const int tid = threadIdx.x;
    const int l   = tid & 31;
    const int jl  = (tid >> 5) * 4 + (l >> 3);   // 0..31
    const int j   = c * 32 + jl;                 // 0..511
    const int gate= (l >> 2) & 1;
    const int ks  = l & 3;

    // U slice in registers: 128 floats (one gate, one j, interleaved k-granules) = 64 ull
    ull U2[64];
    {
        const ulonglong2* up = (const ulonglong2*)(U + (size_t)(gate * 512 + j) * NH) + ks;
#pragma unroll
        for (int q = 0; q < 32; q++) {
            ulonglong2 t = up[q * 4];
            U2[2*q] = t.x; U2[2*q+1] = t.y;
        }
    }

    __shared__ float hsm[2 * NH];       // [b*512 + j]
    __shared__ float Wbuf[2][128];      // [parity][b*64 + gate*32 + jl]
    for (int i = tid; i < 2 * NH; i += 256) hsm[i] = 0.f;

    // Wpre prefetch mapping (tid < 128): pb = LOCAL batch, pbg = GLOBAL batch row
    const int pb  = tid >> 6;
    const int pbg = 2 * g + pb;                  // <-- R5/R6 bug fix: global row
    const int pg  = (tid >> 5) & 1;
    const int pj  = tid & 31;
    float pf = 0.f;
    if (tid < 128) {
        const float* base = g_Wpre + (size_t)pg * 512 + c * 32 + pj;
        Wbuf[0][tid] = __ldg(base + ((size_t)pbg * NT + 0) * DOUT);         // s=0
        pf           = __ldg(base + ((size_t)pbg * NT + 1) * DOUT);         // s=1
    }
    __syncthreads();

    const bool lead = ((l & 7) == 0);
    int* arrp = &g_arrv[g];

#pragma unroll 1
    for (int s = 0; s < NSEQ; s++) {
        // stage W for step s+1, prefetch step s+2
        if (tid < 128) {
            Wbuf[(s + 1) & 1][tid] = pf;
            int s2 = s + 2; if (s2 > NSEQ - 1) s2 = NSEQ - 1;
            int srcb = (s2 < NT) ? pbg : (NB - 1 - pbg);
            int tt   = (s2 < NT) ? s2  : (s2 - NT);
            pf = __ldg(g_Wpre + ((size_t)srcb * NT + tt) * DOUT + pg * 512 + c * 32 + pj);
        }

        // partial dots over interleaved granules, both batches (f32x2)
        ull acc0 = 0ull, acc1 = 0ull;
        {
            const ulonglong2* h0 = (const ulonglong2*)&hsm[0] + ks;
            const ulonglong2* h1 = (const ulonglong2*)&hsm[NH] + ks;
#pragma unroll
            for (int q = 0; q < 32; q++) {
                ulonglong2 v0 = h0[q * 4];
                fma2(acc0, U2[2*q], v0.x); fma2(acc0, U2[2*q+1], v0.y);
                ulonglong2 v1 = h1[q * 4];
                fma2(acc1, U2[2*q], v1.x); fma2(acc1, U2[2*q+1], v1.y);
            }
        }
        float2 q0 = f2unpk(acc0), q1 = f2unpk(acc1);
        float a0 = q0.x + q0.y, a1 = q1.x + q1.y;
        a0 += __shfl_xor_sync(0xffffffffu, a0, 1);
        a1 += __shfl_xor_sync(0xffffffffu, a1, 1);
        a0 += __shfl_xor_sync(0xffffffffu, a0, 2);
        a1 += __shfl_xor_sync(0xffffffffu, a1, 2);
        float o0 = __shfl_xor_sync(0xffffffffu, a0, 4);   // other gate's sum
        float o1 = __shfl_xor_sync(0xffffffffu, a1, 4);

        if (lead) {   // gate==0, ks==0: a=uz, o=uh; 4 leaders/warp
            const float* wb = Wbuf[s & 1];
            float wz0 = wb[jl],       wh0 = wb[32 + jl];
            float wz1 = wb[64 + jl],  wh1 = wb[96 + jl];
            float zt0 = 1.f / (1.f + expf(-(wz0 + a0)));
            float hc0 = fmaxf(wh0 + o0, 0.f);
            float hn0 = zt0 * hsm[j] + (1.f - zt0) * hc0;
            float zt1 = 1.f / (1.f + expf(-(wz1 + a1)));
            float hc1 = fmaxf(wh1 + o1, 0.f);
            float hn1 = zt1 * hsm[NH + j] + (1.f - zt1) * hc1;

            float* hb = &g_hbuf[g][s & 1][0];
            st_relaxed_gpu(hb + j,      hn0);
            st_relaxed_gpu(hb + NH + j, hn1);
            __stcg(g_H + ((size_t)s * NB + 2 * g)     * NH + j, hn0);
            __stcg(g_H + ((size_t)s * NB + 2 * g + 1) * NH + j, hn1);
        }
        __syncthreads();   // all leaders' h stores ordered before the release

        if (tid == 0) {
            asm volatile("red.release.gpu.global.add.s32 [%0], 1;" :: "l"(arrp) : "memory");
            const int target = 16 * (s + 1);
            int v;
            do {
                asm volatile("ld.acquire.gpu.global.s32 %0, [%1];"
                             : "=r"(v) : "l"(arrp) : "memory");
            } while (v < target);
        }
        __syncthreads();   // tid0's acquire ordered before everyone's reload

        {
            const float4* src = (const float4*)&g_hbuf[g][s & 1][0];
            float4 hv = __ldcg(src + tid);
            *(float4*)&hsm[tid * 4] = hv;
        }
        __syncthreads();
    }
}

// ---------------- LayerNorm over gathered bidirectional output ----------------
__global__ __launch_bounds__(256)
void ln_kernel(const float* __restrict__ lng, const float* __restrict__ lnb)
{
    const int r = blockIdx.x;            // 0..15999 = b*1000 + t
    const int b = r / NT, t = r - b * NT;
    const int tid = threadIdx.x;

    const float* s0 = g_H + ((size_t)t * NB + b) * NH;                   // forward
    const float* s1 = g_H + ((size_t)(NT + t) * NB + (NB - 1 - b)) * NH; // backward

    float v0 = s0[tid], v1 = s0[tid + 256];
    float v2 = s1[tid], v3 = s1[tid + 256];

    float s  = v0 + v1 + v2 + v3;
    float sq = v0*v0 + v1*v1 + v2*v2 + v3*v3;

    for (int o = 16; o; o >>= 1) {
        s  += __shfl_down_sync(0xffffffffu, s,  o);
        sq += __shfl_down_sync(0xffffffffu, sq, o);
    }
    __shared__ float rs_[8], rq_[8];
    __shared__ float mu_s, rstd_s;
    if ((tid & 31) == 0) { rs_[tid >> 5] = s; rq_[tid >> 5] = sq; }
    __syncthreads();
    if (tid == 0) {
        float S = 0.f, Q = 0.f;
#pragma unroll
        for (int i = 0; i < 8; i++) { S += rs_[i]; Q += rq_[i]; }
        float mu = S * (1.f / 1024.f);
        float var = Q * (1.f / 1024.f) - mu * mu;
        mu_s = mu;
        rstd_s = rsqrtf(var + 1e-5f);
    }
    __syncthreads();
    const float mu = mu_s, rs = rstd_s;

    float* o = g_ln + (size_t)r * DOUT;
    o[tid]        = (v0 - mu) * rs * lng[tid]        + lnb[tid];
    o[tid + 256]  = (v1 - mu) * rs * lng[tid + 256]  + lnb[tid + 256];
    o[tid + 512]  = (v2 - mu) * rs * lng[tid + 512]  + lnb[tid + 512];
    o[tid + 768]  = (v3 - mu) * rs * lng[tid + 768]  + lnb[tid + 768];
}

// ---------------- x_len passthrough tail ----------------
__global__ void tail_kernel(const int* __restrict__ xl, float* __restrict__ out, int n)
{
    int i = threadIdx.x;
    if (i < n) out[(size_t)MROWS * DOUT + i] = (float)xl[i];
}

// ---------------- launch ----------------
extern "C" void kernel_launch(void* const* d_in, const int* in_sizes, int n_in,
                              void* d_out, int out_size)
{
    const float* x    = (const float*)d_in[0];
    const int*   xlen = (const int*)  d_in[1];
    const float* Wz   = (const float*)d_in[2];
    const float* bz   = (const float*)d_in[3];
    const float* Wh   = (const float*)d_in[4];
    const float* bh   = (const float*)d_in[5];
    const float* U    = (const float*)d_in[6];
    const float* zg   = (const float*)d_in[7];
    const float* zb   = (const float*)d_in[8];
    const float* zm   = (const float*)d_in[9];
    const float* zv   = (const float*)d_in[10];
    const float* hg   = (const float*)d_in[11];
    const float* hbb  = (const float*)d_in[12];
    const float* hm   = (const float*)d_in[13];
    const float* hv   = (const float*)d_in[14];
    const float* lng  = (const float*)d_in[15];
    const float* lnb  = (const float*)d_in[16];
    const float* pjW  = (const float*)d_in[17];
    const float* pjb  = (const float*)d_in[18];
    float* out = (float*)d_out;

    float *Wpre, *lnp, *scl, *shf;
    cudaGetSymbolAddress((void**)&Wpre, g_Wpre);
    cudaGetSymbolAddress((void**)&lnp,  g_ln);
    cudaGetSymbolAddress((void**)&scl,  g_scale);
    cudaGetSymbolAddress((void**)&shf,  g_shift);

    setup_kernel<<<4, 256>>>(bz, bh, zg, zb, zm, zv, hg, hbb, hm, hv);

    dim3 gg(MROWS / GBM, DOUT / GBN);
    gemm_nt2<0><<<gg, 256>>>(x, Wz, Wh, 512, Wpre, MROWS, DOUT, NF, scl, shf);

    dummy_kernel<<<1, 32>>>();   // ncu capture-slot alignment

    ligru_kernel<<<128, 256>>>(U);

    ln_kernel<<<MROWS, 256>>>(lng, lnb);

    gemm_nt2<1><<<gg, 256>>>(lnp, pjW, pjW, DOUT, out, MROWS, DOUT, DOUT, pjb, pjb);

    int tail = out_size - MROWS * DOUT;
    if (tail > 0) tail_kernel<<<1, 32>>>(xlen, out, tail > NB ? NB : tail);
}